// round 1
// baseline (speedup 1.0000x reference)
#include <cuda_runtime.h>

#define T_STEPS 50
#define BATCH   256
#define NS      64
#define NC      32
#define NN      96

// Global scratch for gains (forward pass replays them). __device__ arrays are
// the allowed scratch mechanism (no allocations anywhere).
__device__ float g_K[(size_t)T_STEPS * BATCH * NC * NS];   // [t][b][32][64]
__device__ float g_k[(size_t)T_STEPS * BATCH * NC];        // [t][b][32]

// ---- shared memory layout (floats) ----
#define OFF_V    0                      // V carry, 64 x 65 (padded)
#define OFF_F    (OFF_V   + 64*65)      // F tile,  64 x 96
#define OFF_Q    (OFF_F   + 64*96)      // Q,       96 x 97 (padded)
#define OFF_WU   (OFF_Q   + 96*97)      // union: W(64x96) | K(32x64)+U(64x65)
#define OFF_K    (OFF_WU)
#define OFF_U    (OFF_WU  + 2048)
#define OFF_L    (OFF_WU  + 6208)       // Cholesky L, 32 x 33
#define OFF_ID   (OFF_L   + 32*33)      // inv diag, 32
#define OFF_v    (OFF_ID  + 32)         // v carry, 64
#define OFF_q    (OFF_v   + 64)         // q, 96
#define OFF_xut  (OFF_q   + 96)         // xut, 96
#define OFF_kv   (OFF_xut + 96)         // k vec, 32
#define OFF_x    (OFF_kv  + 32)         // fwd x, 64
#define OFF_dx   (OFF_x   + 64)         // fwd dx, 64
#define OFF_nu   (OFF_dx  + 64)         // fwd new_u, 32
#define SMEM_FLOATS (OFF_nu + 32)
#define SMEM_BYTES  (SMEM_FLOATS * 4)

__global__ __launch_bounds__(256, 2)
void lqr_kernel(const float* __restrict__ x_init,
                const float* __restrict__ Cg,
                const float* __restrict__ cg,
                const float* __restrict__ Fg,
                const float* __restrict__ cxg,
                const float* __restrict__ cug,
                float* __restrict__ out)
{
    extern __shared__ float sm[];
    const int b   = blockIdx.x;
    const int tid = threadIdx.x;

    float* sV  = sm + OFF_V;
    float* sF  = sm + OFF_F;
    float* sQ  = sm + OFF_Q;
    float* sW  = sm + OFF_WU;
    float* sK  = sm + OFF_K;
    float* sU  = sm + OFF_U;
    float* sL  = sm + OFF_L;
    float* sid = sm + OFF_ID;
    float* sv  = sm + OFF_v;
    float* sq  = sm + OFF_q;
    float* sxu = sm + OFF_xut;
    float* skv = sm + OFF_kv;
    float* sx  = sm + OFF_x;
    float* sdx = sm + OFF_dx;
    float* snu = sm + OFF_nu;

    // ---------------- init carries + first F tile ----------------
    for (int i = tid; i < 64 * 65; i += 256) sV[i] = 0.f;
    if (tid < NS) sv[tid] = 0.f;
    {
        const float* Fsrc = Fg + ((size_t)(T_STEPS - 1) * BATCH + b) * (NS * NN);
        for (int i = tid; i < NS * NN; i += 256) sF[i] = Fsrc[i];
    }
    __syncthreads();

    // ================= BACKWARD RICCATI SCAN =================
    for (int t = T_STEPS - 1; t >= 0; --t) {
        const size_t tb = (size_t)t * BATCH + b;

        // load xut (used later by q phase)
        if (tid < NS)            sxu[tid] = cxg[tb * NS + tid];
        else if (tid < NN)       sxu[tid] = cug[tb * NC + (tid - NS)];

        // ---- Phase 1: W = V @ F   (64 x 96, inner 64), 4x6 register tiles ----
        {
            const int ty = tid >> 4, tx = tid & 15;
            const int i0 = ty * 4,  j0 = tx * 6;
            float acc[4][6];
            #pragma unroll
            for (int u = 0; u < 4; ++u)
                #pragma unroll
                for (int v = 0; v < 6; ++v) acc[u][v] = 0.f;
            for (int a = 0; a < 64; ++a) {
                float fv[4], fw[6];
                #pragma unroll
                for (int u = 0; u < 4; ++u) fv[u] = sV[(i0 + u) * 65 + a];
                #pragma unroll
                for (int v = 0; v < 6; ++v) fw[v] = sF[a * 96 + j0 + v];
                #pragma unroll
                for (int u = 0; u < 4; ++u)
                    #pragma unroll
                    for (int v = 0; v < 6; ++v) acc[u][v] += fv[u] * fw[v];
            }
            #pragma unroll
            for (int u = 0; u < 4; ++u)
                #pragma unroll
                for (int v = 0; v < 6; ++v) sW[(i0 + u) * 96 + j0 + v] = acc[u][v];
        }
        __syncthreads();

        // ---- Phase 2: Q = C + F^T @ W  (96 x 96, inner 64), 6x6 tiles ----
        {
            const int ty = tid >> 4, tx = tid & 15;
            const int i0 = ty * 6,  j0 = tx * 6;
            float acc[6][6];
            #pragma unroll
            for (int u = 0; u < 6; ++u)
                #pragma unroll
                for (int v = 0; v < 6; ++v) acc[u][v] = 0.f;
            for (int a = 0; a < 64; ++a) {
                float fa[6], fw[6];
                #pragma unroll
                for (int u = 0; u < 6; ++u) fa[u] = sF[a * 96 + i0 + u];
                #pragma unroll
                for (int v = 0; v < 6; ++v) fw[v] = sW[a * 96 + j0 + v];
                #pragma unroll
                for (int u = 0; u < 6; ++u)
                    #pragma unroll
                    for (int v = 0; v < 6; ++v) acc[u][v] += fa[u] * fw[v];
            }
            const float* Crow = Cg + tb * (NN * NN);
            #pragma unroll
            for (int u = 0; u < 6; ++u)
                #pragma unroll
                for (int v = 0; v < 6; ++v)
                    sQ[(i0 + u) * 97 + j0 + v] =
                        acc[u][v] + Crow[(i0 + u) * 96 + j0 + v];
        }
        __syncthreads();

        // ---- q phase: q[i] = c[i] + (C @ xut)[i] + (F^T v)[i] ----
        if (tid < NN) {
            const float* Crow = Cg + tb * (NN * NN) + (size_t)tid * NN;
            float s = cg[tb * NN + tid];
            #pragma unroll 8
            for (int j = 0; j < NN; ++j) s += Crow[j] * sxu[j];
            float s2 = 0.f;
            #pragma unroll 8
            for (int a = 0; a < NS; ++a) s2 += sF[a * 96 + tid] * sv[a];
            sq[tid] = s + s2;
        }
        __syncthreads();

        // ---- Cholesky of Q_uu (warp 0) | prefetch next F (warps 1..7) ----
        if ((tid >> 5) == 0) {
            const int r = tid & 31;
            float Lr[32];
            #pragma unroll
            for (int kk = 0; kk < 32; ++kk)
                Lr[kk] = sQ[(64 + r) * 97 + 64 + kk];
            #pragma unroll
            for (int j = 0; j < 32; ++j) {
                float s = Lr[j];
                #pragma unroll
                for (int kk = 0; kk < j; ++kk) s -= Lr[kk] * sL[j * 33 + kk];
                float d = sqrtf(__shfl_sync(0xffffffffu, s, j));
                float val = (r == j) ? d : s / d;
                Lr[j] = val;
                if (r >= j) sL[r * 33 + j] = val;
                if (r == j) sid[j] = 1.0f / d;
                __syncwarp();
            }
        } else if (t > 0) {
            const float* Fsrc = Fg + ((size_t)(t - 1) * BATCH + b) * (NS * NN);
            for (int i = tid - 32; i < NS * NN; i += 224) sF[i] = Fsrc[i];
        }
        __syncthreads();

        // ---- triangular solves: Quu y = rhs ; K = -y (64 cols) , k = -y ----
        if (tid < 65) {
            float y[32];
            #pragma unroll
            for (int r2 = 0; r2 < 32; ++r2)
                y[r2] = (tid < 64) ? sQ[(64 + r2) * 97 + tid] : sq[64 + r2];
            #pragma unroll
            for (int j = 0; j < 32; ++j) {               // L y' = rhs
                float s = y[j];
                #pragma unroll
                for (int kk = 0; kk < j; ++kk) s -= sL[j * 33 + kk] * y[kk];
                y[j] = s * sid[j];
            }
            #pragma unroll
            for (int j = 31; j >= 0; --j) {              // L^T z = y'
                float s = y[j];
                #pragma unroll
                for (int kk = j + 1; kk < 32; ++kk) s -= sL[kk * 33 + j] * y[kk];
                y[j] = s * sid[j];
            }
            if (tid < 64) {
                #pragma unroll
                for (int r2 = 0; r2 < 32; ++r2) sK[r2 * 64 + tid] = -y[r2];
            } else {
                #pragma unroll
                for (int r2 = 0; r2 < 32; ++r2) skv[r2] = -y[r2];
            }
        }
        __syncthreads();

        // ---- U = Q_xu @ K (64x64, inner 32), 4x4 tiles ----
        {
            const int ty = tid >> 4, tx = tid & 15;
            const int i0 = ty * 4,  j0 = tx * 4;
            float acc[4][4];
            #pragma unroll
            for (int u = 0; u < 4; ++u)
                #pragma unroll
                for (int v = 0; v < 4; ++v) acc[u][v] = 0.f;
            #pragma unroll 4
            for (int r = 0; r < 32; ++r) {
                float qa[4], kb[4];
                #pragma unroll
                for (int u = 0; u < 4; ++u) qa[u] = sQ[(i0 + u) * 97 + 64 + r];
                #pragma unroll
                for (int v = 0; v < 4; ++v) kb[v] = sK[r * 64 + j0 + v];
                #pragma unroll
                for (int u = 0; u < 4; ++u)
                    #pragma unroll
                    for (int v = 0; v < 4; ++v) acc[u][v] += qa[u] * kb[v];
            }
            #pragma unroll
            for (int u = 0; u < 4; ++u)
                #pragma unroll
                for (int v = 0; v < 4; ++v) sU[(i0 + u) * 65 + j0 + v] = acc[u][v];
        }
        // v_new = q_x + Q_xu @ k   (sv only read by q phase, safely done)
        if (tid < 64) {
            float s = sq[tid];
            #pragma unroll
            for (int r = 0; r < 32; ++r) s += sQ[tid * 97 + 64 + r] * skv[r];
            sv[tid] = s;
        }
        // spill gains for forward pass
        {
            float* gK = g_K + tb * (NC * NS);
            for (int i = tid; i < NC * NS; i += 256) gK[i] = sK[i];
            if (tid < NC) g_k[tb * NC + tid] = skv[tid];
        }
        __syncthreads();

        // ---- Vn = Q_xx + sym(U)  -> sV ----
        {
            const int ty = tid >> 4, tx = tid & 15;
            const int i0 = ty * 4,  j0 = tx * 4;
            #pragma unroll
            for (int u = 0; u < 4; ++u)
                #pragma unroll
                for (int v = 0; v < 4; ++v) {
                    const int i = i0 + u, j = j0 + v;
                    sV[i * 65 + j] = sQ[i * 97 + j]
                                   + 0.5f * (sU[i * 65 + j] + sU[j * 65 + i]);
                }
        }
        __syncthreads();
    }

    // ================= FORWARD ROLLOUT =================
    if (tid < NS) { sx[tid] = x_init[(size_t)b * NS + tid]; sdx[tid] = 0.f; }
    __syncthreads();

    for (int t = 0; t < T_STEPS; ++t) {
        const size_t tb = (size_t)t * BATCH + b;
        {
            const float* gK = g_K + tb * (NC * NS);
            for (int i = tid; i < NC * NS; i += 256) sK[i] = gK[i];
            const float* Fsrc = Fg + tb * (size_t)(NS * NN);
            for (int i = tid; i < NS * NN; i += 256) sF[i] = Fsrc[i];
        }
        __syncthreads();

        if (tid < NC) {   // new_u = K dx + u + k
            float s = g_k[tb * NC + tid] + cug[tb * NC + tid];
            #pragma unroll
            for (int j = 0; j < NS; ++j) {
                int jj = (j + tid) & 63;                 // bank-skew
                s += sK[tid * 64 + jj] * sdx[jj];
            }
            snu[tid] = s;
            out[(size_t)T_STEPS * BATCH * NS + tb * NC + tid] = s;
        }
        if (tid >= 64 && tid < 128) {                    // new_x[t] = x_t
            int i = tid - 64;
            out[tb * NS + i] = sx[i];
        }
        __syncthreads();

        if (tid < NS)            sxu[tid] = sx[tid];
        else if (tid < NN)       sxu[tid] = snu[tid - NS];
        __syncthreads();

        if (tid < NS) {   // x_next = F @ [x; new_u]
            float s = 0.f;
            #pragma unroll
            for (int j = 0; j < NN; ++j) {
                int jj = j + tid; if (jj >= NN) jj -= NN; // bank-skew
                s += sF[tid * 96 + jj] * sxu[jj];
            }
            float xr = (t < T_STEPS - 1)
                     ? cxg[((size_t)(t + 1) * BATCH + b) * NS + tid] : 0.f;
            sx[tid]  = s;
            sdx[tid] = s - xr;
        }
        __syncthreads();
    }
}

extern "C" void kernel_launch(void* const* d_in, const int* in_sizes, int n_in,
                              void* d_out, int out_size)
{
    const float* x_init = (const float*)d_in[0];
    const float* C      = (const float*)d_in[1];
    const float* c      = (const float*)d_in[2];
    const float* F      = (const float*)d_in[3];
    const float* cx     = (const float*)d_in[4];
    const float* cu     = (const float*)d_in[5];

    cudaFuncSetAttribute(lqr_kernel,
                         cudaFuncAttributeMaxDynamicSharedMemorySize, SMEM_BYTES);
    lqr_kernel<<<BATCH, 256, SMEM_BYTES>>>(x_init, C, c, F, cx, cu, (float*)d_out);
}

// round 2
// speedup vs baseline: 1.0340x; 1.0340x over previous
#include <cuda_runtime.h>

#define T_STEPS 50
#define BATCH   256
#define NS      64
#define NC      32
#define NN      96

typedef unsigned long long ull;

// Global scratch for gains (forward pass replays them).
__device__ float g_K[(size_t)T_STEPS * BATCH * NC * NS];   // [t][b][32][64]
__device__ float g_k[(size_t)T_STEPS * BATCH * NC];        // [t][b][32]

// ---- shared memory layout (floats) ----
#define OFF_V    0                      // V carry, 64 x 65 (padded, symmetric)
#define OFF_F    (OFF_V   + 64*65)      // F tile,  64 x 96
#define OFF_Q    (OFF_F   + 64*96)      // Q, 96 x 96 (lower triangle valid)
#define OFF_WU   (OFF_Q   + 96*96)      // union: W(64x96) | K(32x64)+U(64x65)
#define OFF_K    (OFF_WU)
#define OFF_U    (OFF_WU  + 2048)
#define OFF_L    (OFF_WU  + 6208)       // Cholesky workspace, 32 x 33
#define OFF_ID   (OFF_L   + 32*33)      // inv diag, 32
#define OFF_v    (OFF_ID  + 32)         // v carry, 64
#define OFF_q    (OFF_v   + 64)         // q, 96
#define OFF_xut  (OFF_q   + 96)         // xut, 96
#define OFF_kv   (OFF_xut + 96)         // k vec, 32
#define OFF_x    (OFF_kv  + 32)         // fwd x, 64
#define OFF_dx   (OFF_x   + 64)         // fwd dx, 64
#define OFF_nu   (OFF_dx  + 64)         // fwd new_u, 32
#define SMEM_FLOATS (OFF_nu + 32)
#define SMEM_BYTES  (SMEM_FLOATS * 4)

// ---- packed fp32x2 helpers (SASS FFMA2 path) ----
__device__ __forceinline__ ull pk2(float lo, float hi) {
    ull r; asm("mov.b64 %0, {%1, %2};" : "=l"(r) : "f"(lo), "f"(hi)); return r;
}
__device__ __forceinline__ ull dup2(float x) { return pk2(x, x); }
__device__ __forceinline__ void upk2(float& lo, float& hi, ull v) {
    asm("mov.b64 {%0, %1}, %2;" : "=f"(lo), "=f"(hi) : "l"(v));
}
__device__ __forceinline__ void fma2(ull& d, ull a, ull b) {
    asm("fma.rn.f32x2 %0, %2, %3, %1;" : "=l"(d) : "l"(d), "l"(a), "l"(b));
}

__global__ __launch_bounds__(256, 2)
void lqr_kernel(const float* __restrict__ x_init,
                const float* __restrict__ Cg,
                const float* __restrict__ cg,
                const float* __restrict__ Fg,
                const float* __restrict__ cxg,
                const float* __restrict__ cug,
                float* __restrict__ out)
{
    extern __shared__ float sm[];
    const int b   = blockIdx.x;
    const int tid = threadIdx.x;

    float* sV  = sm + OFF_V;
    float* sF  = sm + OFF_F;
    float* sQ  = sm + OFF_Q;
    float* sW  = sm + OFF_WU;
    float* sK  = sm + OFF_K;
    float* sU  = sm + OFF_U;
    float* sL  = sm + OFF_L;
    float* sid = sm + OFF_ID;
    float* sv  = sm + OFF_v;
    float* sq  = sm + OFF_q;
    float* sxu = sm + OFF_xut;
    float* skv = sm + OFF_kv;
    float* sx  = sm + OFF_x;
    float* sdx = sm + OFF_dx;
    float* snu = sm + OFF_nu;

    const int ty = tid >> 4, tx = tid & 15;

    // Static job mapping for triangular phase 2: 6x4 tiles over 96x96,
    // blocks with 6*bi+5 >= 4*bj (208 jobs).  Computed once.
    int p2bi = -1, p2bj = 0;
    {
        int idx = tid;
        #pragma unroll
        for (int r = 0; r < 16; ++r) {
            int cnt = (6 * r + 5) / 4 + 1;
            if (idx < cnt && p2bi < 0) { p2bi = r; p2bj = idx; }
            if (p2bi < 0) idx -= cnt;
        }
    }
    const bool p2a = (p2bi >= 0);

    // ---------------- init carries + first F tile ----------------
    for (int i = tid; i < 64 * 65; i += 256) sV[i] = 0.f;
    if (tid < NS) sv[tid] = 0.f;
    {
        const float* Fsrc = Fg + ((size_t)(T_STEPS - 1) * BATCH + b) * (NS * NN);
        for (int i = tid; i < NS * NN; i += 256) sF[i] = Fsrc[i];
    }
    __syncthreads();

    // ================= BACKWARD RICCATI SCAN =================
    for (int t = T_STEPS - 1; t >= 0; --t) {
        const size_t tb = (size_t)t * BATCH + b;

        // xut (consumed by q phase two barriers later)
        if (tid < NS)       sxu[tid] = cxg[tb * NS + tid];
        else if (tid < NN)  sxu[tid] = cug[tb * NC + (tid - NS)];

        // ---- Phase 1: W = V @ F  (64x96, inner 64), 4x6 tiles, FFMA2 ----
        {
            const int i0 = ty * 4, j0 = tx * 6;
            ull acc[4][3];
            #pragma unroll
            for (int u = 0; u < 4; ++u)
                #pragma unroll
                for (int p = 0; p < 3; ++p) acc[u][p] = 0ull;
            #pragma unroll 4
            for (int a = 0; a < 64; ++a) {
                ull bv[3];
                #pragma unroll
                for (int p = 0; p < 3; ++p)
                    bv[p] = *reinterpret_cast<const ull*>(&sF[a * 96 + j0 + 2 * p]);
                float av[4];
                #pragma unroll
                for (int u = 0; u < 4; ++u) av[u] = sV[a * 65 + i0 + u]; // V symmetric
                #pragma unroll
                for (int u = 0; u < 4; ++u) {
                    ull ad = dup2(av[u]);
                    #pragma unroll
                    for (int p = 0; p < 3; ++p) fma2(acc[u][p], ad, bv[p]);
                }
            }
            #pragma unroll
            for (int u = 0; u < 4; ++u)
                #pragma unroll
                for (int p = 0; p < 3; ++p)
                    *reinterpret_cast<ull*>(&sW[(i0 + u) * 96 + j0 + 2 * p]) = acc[u][p];
        }
        __syncthreads();

        // ---- Phase 2: lower triangle of Q = C + F^T W, 6x4 tiles, FFMA2 ----
        if (p2a) {
            const int i0 = p2bi * 6, j0 = p2bj * 4;
            ull acc[3][4];
            #pragma unroll
            for (int m = 0; m < 3; ++m)
                #pragma unroll
                for (int v = 0; v < 4; ++v) acc[m][v] = 0ull;
            #pragma unroll 4
            for (int a = 0; a < 64; ++a) {
                ull am[3];
                #pragma unroll
                for (int m = 0; m < 3; ++m)
                    am[m] = *reinterpret_cast<const ull*>(&sF[a * 96 + i0 + 2 * m]);
                float4 wb = *reinterpret_cast<const float4*>(&sW[a * 96 + j0]);
                ull wd[4] = { dup2(wb.x), dup2(wb.y), dup2(wb.z), dup2(wb.w) };
                #pragma unroll
                for (int m = 0; m < 3; ++m)
                    #pragma unroll
                    for (int v = 0; v < 4; ++v) fma2(acc[m][v], am[m], wd[v]);
            }
            const float* Crow = Cg + tb * (NN * NN);
            #pragma unroll
            for (int m = 0; m < 3; ++m) {
                float r0[4], r1[4];
                #pragma unroll
                for (int v = 0; v < 4; ++v) upk2(r0[v], r1[v], acc[m][v]);
                float4 c0 = *reinterpret_cast<const float4*>(&Crow[(i0 + 2 * m) * 96 + j0]);
                float4 c1 = *reinterpret_cast<const float4*>(&Crow[(i0 + 2 * m + 1) * 96 + j0]);
                float4 o0 = make_float4(r0[0] + c0.x, r0[1] + c0.y, r0[2] + c0.z, r0[3] + c0.w);
                float4 o1 = make_float4(r1[0] + c1.x, r1[1] + c1.y, r1[2] + c1.z, r1[3] + c1.w);
                *reinterpret_cast<float4*>(&sQ[(i0 + 2 * m) * 96 + j0]) = o0;
                *reinterpret_cast<float4*>(&sQ[(i0 + 2 * m + 1) * 96 + j0]) = o1;
            }
        }
        __syncthreads();

        // ---- q phase (tid<96) | stage Quu into 33-stride buffer (tid>=128) ----
        if (tid < NN) {
            const float* Crow = Cg + tb * (NN * NN) + (size_t)tid * NN;
            float s = cg[tb * NN + tid];
            #pragma unroll 8
            for (int j = 0; j < NN; ++j) s += Crow[j] * sxu[j];
            float s2 = 0.f;
            #pragma unroll 8
            for (int a = 0; a < NS; ++a) s2 += sF[a * 96 + tid] * sv[a];
            sq[tid] = s + s2;
        } else if (tid >= 128) {
            const int i = tid - 128;          // 128 threads, 8 elems each
            const int u = i >> 2;             // row 0..31
            const int c0 = (i & 3) * 8;       // col block
            float4 a0 = *reinterpret_cast<const float4*>(&sQ[(64 + u) * 96 + 64 + c0]);
            float4 a1 = *reinterpret_cast<const float4*>(&sQ[(64 + u) * 96 + 64 + c0 + 4]);
            sL[u * 33 + c0 + 0] = a0.x; sL[u * 33 + c0 + 1] = a0.y;
            sL[u * 33 + c0 + 2] = a0.z; sL[u * 33 + c0 + 3] = a0.w;
            sL[u * 33 + c0 + 4] = a1.x; sL[u * 33 + c0 + 5] = a1.y;
            sL[u * 33 + c0 + 6] = a1.z; sL[u * 33 + c0 + 7] = a1.w;
        }
        __syncthreads();

        // ---- Cholesky of Q_uu in-place in sL (warp 0) | prefetch next F ----
        if ((tid >> 5) == 0) {
            const int r = tid & 31;
            float Lr[32];
            #pragma unroll
            for (int kk = 0; kk < 32; ++kk) Lr[kk] = sL[r * 33 + kk];
            #pragma unroll
            for (int j = 0; j < 32; ++j) {
                float s = Lr[j];
                #pragma unroll
                for (int kk = 0; kk < j; ++kk) s -= Lr[kk] * sL[j * 33 + kk];
                float d = sqrtf(__shfl_sync(0xffffffffu, s, j));
                float val = (r == j) ? d : s / d;
                Lr[j] = val;
                if (r >= j) sL[r * 33 + j] = val;
                if (r == j) sid[j] = 1.0f / d;
                __syncwarp();
            }
        } else if (t > 0) {
            const float* Fsrc = Fg + ((size_t)(t - 1) * BATCH + b) * (NS * NN);
            for (int i = tid - 32; i < NS * NN; i += 224) sF[i] = Fsrc[i];
        }
        __syncthreads();

        // ---- triangular solves: Quu y = rhs ; K = -y (64 cols), k = -y ----
        if (tid < 65) {
            float y[32];
            #pragma unroll
            for (int r2 = 0; r2 < 32; ++r2)
                y[r2] = (tid < 64) ? sQ[(64 + r2) * 96 + tid] : sq[64 + r2];
            #pragma unroll
            for (int j = 0; j < 32; ++j) {               // L y' = rhs
                float s = y[j];
                #pragma unroll
                for (int kk = 0; kk < j; ++kk) s -= sL[j * 33 + kk] * y[kk];
                y[j] = s * sid[j];
            }
            #pragma unroll
            for (int j = 31; j >= 0; --j) {              // L^T z = y'
                float s = y[j];
                #pragma unroll
                for (int kk = j + 1; kk < 32; ++kk) s -= sL[kk * 33 + j] * y[kk];
                y[j] = s * sid[j];
            }
            if (tid < 64) {
                #pragma unroll
                for (int r2 = 0; r2 < 32; ++r2) sK[r2 * 64 + tid] = -y[r2];
            } else {
                #pragma unroll
                for (int r2 = 0; r2 < 32; ++r2) skv[r2] = -y[r2];
            }
        }
        __syncthreads();

        // ---- U = Q_xu @ K = Q_ux^T @ K  (64x64, inner 32), 4x4 tiles, FFMA2 ----
        {
            const int i0 = ty * 4, j0 = tx * 4;
            ull acc[4][2];
            #pragma unroll
            for (int u = 0; u < 4; ++u) { acc[u][0] = 0ull; acc[u][1] = 0ull; }
            #pragma unroll 4
            for (int r = 0; r < 32; ++r) {
                float4 qa = *reinterpret_cast<const float4*>(&sQ[(64 + r) * 96 + i0]);
                float4 kb = *reinterpret_cast<const float4*>(&sK[r * 64 + j0]);
                ull kb2[2] = { pk2(kb.x, kb.y), pk2(kb.z, kb.w) };
                ull q0 = dup2(qa.x), q1 = dup2(qa.y), q2 = dup2(qa.z), q3 = dup2(qa.w);
                fma2(acc[0][0], q0, kb2[0]); fma2(acc[0][1], q0, kb2[1]);
                fma2(acc[1][0], q1, kb2[0]); fma2(acc[1][1], q1, kb2[1]);
                fma2(acc[2][0], q2, kb2[0]); fma2(acc[2][1], q2, kb2[1]);
                fma2(acc[3][0], q3, kb2[0]); fma2(acc[3][1], q3, kb2[1]);
            }
            #pragma unroll
            for (int u = 0; u < 4; ++u) {
                float v0, v1, v2, v3;
                upk2(v0, v1, acc[u][0]); upk2(v2, v3, acc[u][1]);
                sU[(i0 + u) * 65 + j0 + 0] = v0; sU[(i0 + u) * 65 + j0 + 1] = v1;
                sU[(i0 + u) * 65 + j0 + 2] = v2; sU[(i0 + u) * 65 + j0 + 3] = v3;
            }
        }
        // v_new = q_x + Q_xu @ k  (Q_ux column access, conflict-free)
        if (tid < 64) {
            float s = sq[tid];
            #pragma unroll
            for (int r = 0; r < 32; ++r) s += sQ[(64 + r) * 96 + tid] * skv[r];
            sv[tid] = s;
        }
        // spill gains for forward pass
        {
            float* gK = g_K + tb * (NC * NS);
            for (int i = tid; i < NC * NS; i += 256) gK[i] = sK[i];
            if (tid < NC) g_k[tb * NC + tid] = skv[tid];
        }
        __syncthreads();

        // ---- Vn lower triangle + mirror: Vn = Q_xx + sym(U) ----
        if (ty >= tx) {
            const int i0 = ty * 4, j0 = tx * 4;
            #pragma unroll
            for (int u = 0; u < 4; ++u)
                #pragma unroll
                for (int v = 0; v < 4; ++v) {
                    const int i = i0 + u, j = j0 + v;
                    if (i >= j) {
                        float val = sQ[i * 96 + j]
                                  + 0.5f * (sU[i * 65 + j] + sU[j * 65 + i]);
                        sV[i * 65 + j] = val;
                        sV[j * 65 + i] = val;
                    }
                }
        }
        __syncthreads();
    }

    // ================= FORWARD ROLLOUT =================
    if (tid < NS) { sx[tid] = x_init[(size_t)b * NS + tid]; sdx[tid] = 0.f; }
    __syncthreads();

    for (int t = 0; t < T_STEPS; ++t) {
        const size_t tb = (size_t)t * BATCH + b;
        {
            const float* gK = g_K + tb * (NC * NS);
            for (int i = tid; i < NC * NS; i += 256) sK[i] = gK[i];
            const float* Fsrc = Fg + tb * (size_t)(NS * NN);
            for (int i = tid; i < NS * NN; i += 256) sF[i] = Fsrc[i];
        }
        __syncthreads();

        if (tid < NC) {   // new_u = K dx + u + k
            float s = g_k[tb * NC + tid] + cug[tb * NC + tid];
            #pragma unroll
            for (int j = 0; j < NS; ++j) {
                int jj = (j + tid) & 63;                 // bank-skew
                s += sK[tid * 64 + jj] * sdx[jj];
            }
            snu[tid] = s;
            out[(size_t)T_STEPS * BATCH * NS + tb * NC + tid] = s;
        }
        if (tid >= 64 && tid < 128) {                    // new_x[t] = x_t
            int i = tid - 64;
            out[tb * NS + i] = sx[i];
        }
        __syncthreads();

        if (tid < NS)       sxu[tid] = sx[tid];
        else if (tid < NN)  sxu[tid] = snu[tid - NS];
        __syncthreads();

        if (tid < NS) {   // x_next = F @ [x; new_u]
            float s = 0.f;
            #pragma unroll
            for (int j = 0; j < NN; ++j) {
                int jj = j + tid; if (jj >= NN) jj -= NN; // bank-skew
                s += sF[tid * 96 + jj] * sxu[jj];
            }
            float xr = (t < T_STEPS - 1)
                     ? cxg[((size_t)(t + 1) * BATCH + b) * NS + tid] : 0.f;
            sx[tid]  = s;
            sdx[tid] = s - xr;
        }
        __syncthreads();
    }
}

extern "C" void kernel_launch(void* const* d_in, const int* in_sizes, int n_in,
                              void* d_out, int out_size)
{
    const float* x_init = (const float*)d_in[0];
    const float* C      = (const float*)d_in[1];
    const float* c      = (const float*)d_in[2];
    const float* F      = (const float*)d_in[3];
    const float* cx     = (const float*)d_in[4];
    const float* cu     = (const float*)d_in[5];

    cudaFuncSetAttribute(lqr_kernel,
                         cudaFuncAttributeMaxDynamicSharedMemorySize, SMEM_BYTES);
    lqr_kernel<<<BATCH, 256, SMEM_BYTES>>>(x_init, C, c, F, cx, cu, (float*)d_out);
}